// round 16
// baseline (speedup 1.0000x reference)
#include <cuda_runtime.h>
#include <cstdint>

// ---------------------------------------------------------------------------
// Problem constants
// ---------------------------------------------------------------------------
#define S_LEN   2048
#define L_LEN   10240        // 5*S
#define DIM     512
#define PROJ    128
#define KDIM    136          // PROJ + NPOS
#define KPAD    160          // KDIM padded to multiple of 32
#define HEADS   4
#define HD      128
#define PROJ5   2560         // DIM*5
#define KVN     1024         // merged k+v output width

// ---------------------------------------------------------------------------
// Static device scratch
// ---------------------------------------------------------------------------
__device__ float g_src  [S_LEN * KPAD];
__device__ float g_tgt  [L_LEN * DIM];
__device__ float g_q    [L_LEN * DIM];     // reused as skip buffer
__device__ float g_kv   [S_LEN * KVN];     // cols 0-511 = k, 512-1023 = v
__device__ float g_o    [L_LEN * DIM];
__device__ float g_ao   [L_LEN * DIM];
__device__ float g_cnn  [L_LEN * DIM];
__device__ float g_h1   [L_LEN * DIM];
__device__ float g_h2   [L_LEN * DIM];
__device__ float g_projP[PROJ5 * KPAD];
__device__ float g_kvwP [KVN * KPAD];      // rows 0-511 = k_w, 512-1023 = v_w
__device__ float g_qwR  [DIM * DIM];
__device__ float g_outwR[DIM * DIM];
__device__ float g_skipwR[DIM * DIM];
__device__ float g_convR[3 * 3 * DIM * DIM];   // [layer][tap][co][ci]

// ---------------------------------------------------------------------------
// PTX helpers (baseline sm_80+: mma.sync, cp.async, ldmatrix)
// ---------------------------------------------------------------------------
__device__ __forceinline__ uint32_t smem_u32(const void* p) {
    return (uint32_t)__cvta_generic_to_shared(p);
}

__device__ __forceinline__ void cp_async16(uint32_t dst, const void* src, int sz) {
    asm volatile("cp.async.cg.shared.global [%0], [%1], 16, %2;"
                 :: "r"(dst), "l"(src), "r"(sz) : "memory");
}
#define CP_COMMIT() asm volatile("cp.async.commit_group;" ::: "memory")
#define CP_WAIT(n)  asm volatile("cp.async.wait_group %0;" :: "n"(n) : "memory")

__device__ __forceinline__ uint32_t f2tf32(float f) {
    uint32_t r;
    asm("cvt.rna.tf32.f32 %0, %1;" : "=r"(r) : "f"(f));
    return r;
}
__device__ __forceinline__ float roundtf(float f) {
    return __uint_as_float(f2tf32(f));
}

__device__ __forceinline__ void mma_tf32(float* c, const uint32_t* a, const uint32_t* b) {
    asm volatile(
        "mma.sync.aligned.m16n8k8.row.col.f32.tf32.tf32.f32 "
        "{%0,%1,%2,%3}, {%4,%5,%6,%7}, {%8,%9}, {%0,%1,%2,%3};"
        : "+f"(c[0]), "+f"(c[1]), "+f"(c[2]), "+f"(c[3])
        : "r"(a[0]), "r"(a[1]), "r"(a[2]), "r"(a[3]), "r"(b[0]), "r"(b[1]));
}

#define LDMATRIX_X4(r0, r1, r2, r3, addr) \
    asm volatile("ldmatrix.sync.aligned.m8n8.x4.shared.b16 {%0,%1,%2,%3}, [%4];" \
                 : "=r"(r0), "=r"(r1), "=r"(r2), "=r"(r3) : "r"(addr))

// ---------------------------------------------------------------------------
// tf32 tensor-core GEMM, ldmatrix + REGISTER DOUBLE-BUFFERED fragments:
// kk+1 fragments are loaded before kk's MMAs issue, hiding LDS latency
// behind the MMA burst (within-warp ILP; R15 showed warp-count doesn't help).
// 3-stage cp.async pipeline, 256 threads, warp grid 2(M)x4(N), tile 64x32.
// C[M,N] = A[M,K] @ B^T + bias (B: [TAPS][N][K] row-major).
// ALL GEMM inputs pre-rounded to tf32 -> raw fp32 bits feed mma.sync exactly.
// TAPS==3: conv1d k=3 pad=1 (A rows shifted by tap-1, zero at edges)
// SP: softplus epilogue.  ROUND: round outputs to tf32 (for GEMM consumers).
// ---------------------------------------------------------------------------
#define BM 128
#define BN 128
#define BK 32
#define NSTAGE 3
#define NTHREADS 256
#define SSTR 36
#define TILE_F   (128 * SSTR)              // floats per operand tile
#define STAGE_F  (2 * TILE_F)              // A + B
#define SMEM_TC  (NSTAGE * STAGE_F * 4)    // 110592 bytes

__device__ __forceinline__ float softplus_f(float x) {
    return fmaxf(x, 0.0f) + log1pf(expf(-fabsf(x)));
}

template<int TAPS, bool SP, bool ROUND>
__global__ __launch_bounds__(NTHREADS, 1)
void mma_gemm_kernel(const float* __restrict__ A, const float* __restrict__ Bw,
                     const float* __restrict__ bias, float* __restrict__ C,
                     int M, int N, int K) {
    extern __shared__ __align__(16) float smem[];
    const int tid = threadIdx.x;
    const int wid = tid >> 5, lane = tid & 31;
    const int g = lane >> 2, t4 = lane & 3;
    const int wm = wid >> 2, wn = wid & 3;       // 2 x 4 warp grid
    const int row0 = blockIdx.y * BM, col0 = blockIdx.x * BN;

    // per-lane ldmatrix base offsets (bytes) within the A / B tiles
    const int a_row = wm * 64 + (lane & 15);
    const int a_col = (lane >> 4) * 4;
    const uint32_t a_lane_off = (uint32_t)(a_row * SSTR + a_col) * 4;
    const int b_row = wn * 32 + (lane & 7) + ((lane >> 4) & 1) * 8;
    const int b_col = ((lane >> 3) & 1) * 4;
    const uint32_t b_lane_off = (uint32_t)(b_row * SSTR + b_col) * 4;
    const uint32_t smem_b32 = smem_u32(smem);

    float acc[4][4][4];
    #pragma unroll
    for (int i = 0; i < 4; i++)
        #pragma unroll
        for (int j = 0; j < 4; j++)
            #pragma unroll
            for (int r = 0; r < 4; r++) acc[i][j][r] = 0.0f;

    const int kc = K / BK;
    const int nc = kc * TAPS;

    auto load = [&](int c, int s) {
        const int tap = (TAPS == 3) ? (c / kc) : 0;
        const int k0 = (c - tap * kc) * BK;
        float* base = smem + s * STAGE_F;
        #pragma unroll
        for (int t = 0; t < 4; t++) {
            int u = tid + t * NTHREADS;
            int r = u >> 3, ch = u & 7;
            uint32_t dst = smem_u32(base + r * SSTR + ch * 4);
            int arow = row0 + r + (TAPS == 3 ? tap - 1 : 0);
            const float* src = A;
            int sz = 0;
            if (!(TAPS == 3) || (arow >= 0 && arow < M)) {
                src = A + (size_t)arow * K + k0 + ch * 4;
                sz = 16;
            }
            cp_async16(dst, src, sz);
        }
        const float* Bt = Bw + (TAPS == 3 ? (size_t)tap * N * K : 0);
        #pragma unroll
        for (int t = 0; t < 4; t++) {
            int u = tid + t * NTHREADS;
            int r = u >> 3, ch = u & 7;
            uint32_t dst = smem_u32(base + TILE_F + r * SSTR + ch * 4);
            const float* src = Bt + (size_t)(col0 + r) * K + k0 + ch * 4;
            cp_async16(dst, src, 16);
        }
        CP_COMMIT();
    };

    load(0, 0);
    load(1, 1);

    uint32_t af[2][4][4];     // [buf][mi][frag]
    uint32_t bf[2][4][2];     // [buf][nj][frag]

    int stage = 0;
    for (int c = 0; c < nc; c++) {
        CP_WAIT(1);                      // in-order groups: chunk c resident
        __syncthreads();                 // all warps done with stage (c+2)%NSTAGE
        if (c + 2 < nc) load(c + 2, (c + 2) % NSTAGE);
        else CP_COMMIT();                // keep group count constant for CP_WAIT(1)

        const uint32_t sbase = smem_b32 + (uint32_t)(stage * STAGE_F * 4);
        const uint32_t a_base = sbase + a_lane_off;
        const uint32_t b_base = sbase + (uint32_t)(TILE_F * 4) + b_lane_off;

        // prime fragment buffer 0 with kk=0
        #pragma unroll
        for (int i = 0; i < 4; i++)
            LDMATRIX_X4(af[0][i][0], af[0][i][1], af[0][i][2], af[0][i][3],
                        a_base + (uint32_t)(i * 16 * SSTR * 4));
        #pragma unroll
        for (int p = 0; p < 2; p++)
            LDMATRIX_X4(bf[0][2 * p][0], bf[0][2 * p][1],
                        bf[0][2 * p + 1][0], bf[0][2 * p + 1][1],
                        b_base + (uint32_t)(p * 16 * SSTR * 4));

        #pragma unroll
        for (int kk = 0; kk < 4; kk++) {
            const int cur = kk & 1, nxt = cur ^ 1;
            if (kk < 3) {   // prefetch kk+1 fragments BEFORE issuing kk's MMAs
                #pragma unroll
                for (int i = 0; i < 4; i++)
                    LDMATRIX_X4(af[nxt][i][0], af[nxt][i][1], af[nxt][i][2], af[nxt][i][3],
                                a_base + (uint32_t)(i * 16 * SSTR * 4)
                                       + (uint32_t)((kk + 1) * 32));
                #pragma unroll
                for (int p = 0; p < 2; p++)
                    LDMATRIX_X4(bf[nxt][2 * p][0], bf[nxt][2 * p][1],
                                bf[nxt][2 * p + 1][0], bf[nxt][2 * p + 1][1],
                                b_base + (uint32_t)(p * 16 * SSTR * 4)
                                       + (uint32_t)((kk + 1) * 32));
            }
            #pragma unroll
            for (int i = 0; i < 4; i++)
                #pragma unroll
                for (int j = 0; j < 4; j++)
                    mma_tf32(acc[i][j], af[cur][i], bf[cur][j]);
        }
        stage = (stage + 1 < NSTAGE) ? stage + 1 : 0;
    }

    // epilogue: bias (+softplus) (+tf32 round), direct float2 stores
    #pragma unroll
    for (int i = 0; i < 4; i++) {
        const int m = row0 + wm * 64 + i * 16 + g;
        #pragma unroll
        for (int j = 0; j < 4; j++) {
            const int n = col0 + wn * 32 + j * 8 + 2 * t4;
            const float b0 = bias[n], b1 = bias[n + 1];
            float v0 = acc[i][j][0] + b0, v1 = acc[i][j][1] + b1;
            float v2 = acc[i][j][2] + b0, v3 = acc[i][j][3] + b1;
            if (SP) {
                v0 = softplus_f(v0); v1 = softplus_f(v1);
                v2 = softplus_f(v2); v3 = softplus_f(v3);
            }
            if (ROUND) {
                v0 = roundtf(v0); v1 = roundtf(v1);
                v2 = roundtf(v2); v3 = roundtf(v3);
            }
            *(float2*)(C + (size_t)m * N + n)       = make_float2(v0, v1);
            *(float2*)(C + (size_t)(m + 8) * N + n) = make_float2(v2, v3);
        }
    }
}

// ---------------------------------------------------------------------------
// Fused prep kernel: all input conditioning in one launch (range-dispatched).
// ---------------------------------------------------------------------------
#define PREP_SRC    (S_LEN * KPAD)
#define PREP_PROJ   (PROJ5 * KPAD)
#define PREP_KVW    (KVN * KPAD)
#define PREP_W      (DIM * DIM)
#define PREP_CONV   (3 * 3 * DIM * DIM)
#define PREP_TOTAL  (PREP_SRC + PREP_PROJ + PREP_KVW + 3 * PREP_W + PREP_CONV)

__global__ void prep_all_kernel(const float* __restrict__ x,
                                const float* __restrict__ proj_w,
                                const float* __restrict__ k_w,
                                const float* __restrict__ v_w,
                                const float* __restrict__ q_w,
                                const float* __restrict__ out_w,
                                const float* __restrict__ skip_w,
                                const float* __restrict__ conv_w,
                                float* __restrict__ src,
                                float* __restrict__ projP,
                                float* __restrict__ kvwP,
                                float* __restrict__ qwR,
                                float* __restrict__ outwR,
                                float* __restrict__ skipwR,
                                float* __restrict__ convR) {
    int idx = blockIdx.x * blockDim.x + threadIdx.x;
    if (idx >= PREP_TOTAL) return;
    if (idx < PREP_SRC) {
        int n = idx / KPAD, c = idx % KPAD;
        float val = 0.0f;
        if (c < PROJ) val = roundtf(x[n * PROJ + c]);
        else if (c < KDIM) {
            int e = c - PROJ;
            int mod = n & ((2 << e) - 1);
            val = (float)mod / (float)(1 << e);
        }
        src[idx] = val;
        return;
    }
    idx -= PREP_SRC;
    if (idx < PREP_PROJ) {
        int r = idx / KPAD, c = idx % KPAD;
        projP[idx] = (c < KDIM) ? roundtf(proj_w[r * KDIM + c]) : 0.0f;
        return;
    }
    idx -= PREP_PROJ;
    if (idx < PREP_KVW) {
        int r = idx / KPAD, c = idx % KPAD;
        const float* W = (r < DIM) ? k_w : v_w;
        int rr = (r < DIM) ? r : r - DIM;
        kvwP[idx] = (c < KDIM) ? roundtf(W[rr * KDIM + c]) : 0.0f;
        return;
    }
    idx -= PREP_KVW;
    if (idx < PREP_W) { qwR[idx] = roundtf(q_w[idx]); return; }
    idx -= PREP_W;
    if (idx < PREP_W) { outwR[idx] = roundtf(out_w[idx]); return; }
    idx -= PREP_W;
    if (idx < PREP_W) { skipwR[idx] = roundtf(skip_w[idx]); return; }
    idx -= PREP_W;
    {   // conv_w[li][co][ci][t] -> convR[li][t][co][ci]
        int ci = idx & (DIM - 1);
        int co = (idx >> 9) & (DIM - 1);
        int t  = (idx / (DIM * DIM)) % 3;
        int li = idx / (3 * DIM * DIM);
        convR[idx] = roundtf(conv_w[(((size_t)li * DIM + co) * DIM + ci) * 3 + t]);
    }
}

// ---------------------------------------------------------------------------
// Banded attention (band width <= 27): one block/query, one warp/head.
// k = kv[:, 0:512], v = kv[:, 512:1024]
// ---------------------------------------------------------------------------
__global__ void banded_attn_kernel(const float* __restrict__ q, const float* __restrict__ kv,
                                   float* __restrict__ o) {
    int l = blockIdx.x;
    int h = threadIdx.y;
    int lane = threadIdx.x;
    int i_min = l > 64 ? (l - 64) / 5 : 0;
    int i_max = (l + 64) / 5;
    if (i_max > S_LEN - 1) i_max = S_LEN - 1;
    int cnt = i_max - i_min + 1;

    float4 qr = ((const float4*)(q + (size_t)l * DIM + h * HD))[lane];
    const float scale = 0.0883883476483184f;

    float myscore = -1e30f;
    for (int j = 0; j < cnt; j++) {
        const float4 kr = ((const float4*)(kv + (size_t)(i_min + j) * KVN + h * HD))[lane];
        float d = qr.x * kr.x + qr.y * kr.y + qr.z * kr.z + qr.w * kr.w;
        #pragma unroll
        for (int off = 16; off; off >>= 1) d += __shfl_xor_sync(0xffffffffu, d, off);
        if (lane == j) myscore = d * scale;
    }
    float val = (lane < cnt) ? myscore : -1e30f;
    float mx = val;
    #pragma unroll
    for (int off = 16; off; off >>= 1)
        mx = fmaxf(mx, __shfl_xor_sync(0xffffffffu, mx, off));
    float e = (lane < cnt) ? expf(val - mx) : 0.0f;
    float sum = e;
    #pragma unroll
    for (int off = 16; off; off >>= 1) sum += __shfl_xor_sync(0xffffffffu, sum, off);
    float a = e / sum;

    float4 acc = make_float4(0.f, 0.f, 0.f, 0.f);
    for (int j = 0; j < cnt; j++) {
        float aj = __shfl_sync(0xffffffffu, a, j);
        const float4 vr = ((const float4*)(kv + (size_t)(i_min + j) * KVN + DIM + h * HD))[lane];
        acc.x += aj * vr.x; acc.y += aj * vr.y;
        acc.z += aj * vr.z; acc.w += aj * vr.w;
    }
    acc.x = roundtf(acc.x); acc.y = roundtf(acc.y);
    acc.z = roundtf(acc.z); acc.w = roundtf(acc.w);
    ((float4*)(o + (size_t)l * DIM + h * HD))[lane] = acc;
}

// ---------------------------------------------------------------------------
// LayerNorm kernels
// ---------------------------------------------------------------------------
__device__ __forceinline__ void block_reduce_2(float& s, float& s2, int t) {
    #pragma unroll
    for (int off = 16; off; off >>= 1) {
        s  += __shfl_xor_sync(0xffffffffu, s,  off);
        s2 += __shfl_xor_sync(0xffffffffu, s2, off);
    }
    __shared__ float ss[4], ss2[4];
    if ((t & 31) == 0) { ss[t >> 5] = s; ss2[t >> 5] = s2; }
    __syncthreads();
    s  = ss[0] + ss[1] + ss[2] + ss[3];
    s2 = ss2[0] + ss2[1] + ss2[2] + ss2[3];
}

__global__ void ln_add_kernel(const float* __restrict__ z, const float* __restrict__ res,
                              float* __restrict__ out) {
    int r = blockIdx.x;
    int t = threadIdx.x;
    float4 xv = ((const float4*)(z + (size_t)r * DIM))[t];
    float s  = xv.x + xv.y + xv.z + xv.w;
    float s2 = xv.x * xv.x + xv.y * xv.y + xv.z * xv.z + xv.w * xv.w;
    block_reduce_2(s, s2, t);
    float m = s * (1.0f / DIM);
    float var = s2 * (1.0f / DIM) - m * m;
    float rstd = rsqrtf(var + 1e-5f);
    float4 rv = ((const float4*)(res + (size_t)r * DIM))[t];
    float4 ov;
    ov.x = roundtf((xv.x - m) * rstd + rv.x);
    ov.y = roundtf((xv.y - m) * rstd + rv.y);
    ov.z = roundtf((xv.z - m) * rstd + rv.z);
    ov.w = roundtf((xv.w - m) * rstd + rv.w);
    ((float4*)(out + (size_t)r * DIM))[t] = ov;
}

__global__ void add_ln_kernel(const float* __restrict__ h, const float* __restrict__ sk,
                              float* __restrict__ out) {
    int r = blockIdx.x;
    int t = threadIdx.x;
    float4 hv = ((const float4*)(h  + (size_t)r * DIM))[t];
    float4 kv = ((const float4*)(sk + (size_t)r * DIM))[t];
    float4 xv;
    xv.x = hv.x + kv.x; xv.y = hv.y + kv.y; xv.z = hv.z + kv.z; xv.w = hv.w + kv.w;
    float s  = xv.x + xv.y + xv.z + xv.w;
    float s2 = xv.x * xv.x + xv.y * xv.y + xv.z * xv.z + xv.w * xv.w;
    block_reduce_2(s, s2, t);
    float m = s * (1.0f / DIM);
    float var = s2 * (1.0f / DIM) - m * m;
    float rstd = rsqrtf(var + 1e-5f);
    float4 ov;
    ov.x = (xv.x - m) * rstd;
    ov.y = (xv.y - m) * rstd;
    ov.z = (xv.z - m) * rstd;
    ov.w = (xv.w - m) * rstd;
    ((float4*)(out + (size_t)r * DIM))[t] = ov;
}

// ---------------------------------------------------------------------------
// Launch
// ---------------------------------------------------------------------------
extern "C" void kernel_launch(void* const* d_in, const int* in_sizes, int n_in,
                              void* d_out, int out_size) {
    const float* x        = (const float*)d_in[0];
    const float* residual = (const float*)d_in[1];
    const float* proj_w   = (const float*)d_in[2];
    const float* proj_b   = (const float*)d_in[3];
    const float* q_w      = (const float*)d_in[4];
    const float* k_w      = (const float*)d_in[5];
    const float* v_w      = (const float*)d_in[6];
    const float* in_b     = (const float*)d_in[7];
    const float* out_w    = (const float*)d_in[8];
    const float* out_b    = (const float*)d_in[9];
    const float* conv_w   = (const float*)d_in[10];
    const float* conv_b   = (const float*)d_in[11];
    const float* skip_w   = (const float*)d_in[12];
    const float* skip_b   = (const float*)d_in[13];
    float* out = (float*)d_out;

    float *src, *tgt, *q, *kv, *o, *ao, *cnn, *h1, *h2;
    float *projP, *kvwP, *qwR, *outwR, *skipwR, *convR;
    cudaGetSymbolAddress((void**)&src,    g_src);
    cudaGetSymbolAddress((void**)&tgt,    g_tgt);
    cudaGetSymbolAddress((void**)&q,      g_q);
    cudaGetSymbolAddress((void**)&kv,     g_kv);
    cudaGetSymbolAddress((void**)&o,      g_o);
    cudaGetSymbolAddress((void**)&ao,     g_ao);
    cudaGetSymbolAddress((void**)&cnn,    g_cnn);
    cudaGetSymbolAddress((void**)&h1,     g_h1);
    cudaGetSymbolAddress((void**)&h2,     g_h2);
    cudaGetSymbolAddress((void**)&projP,  g_projP);
    cudaGetSymbolAddress((void**)&kvwP,   g_kvwP);
    cudaGetSymbolAddress((void**)&qwR,    g_qwR);
    cudaGetSymbolAddress((void**)&outwR,  g_outwR);
    cudaGetSymbolAddress((void**)&skipwR, g_skipwR);
    cudaGetSymbolAddress((void**)&convR,  g_convR);

    cudaFuncSetAttribute(mma_gemm_kernel<1, false, true>,
                         cudaFuncAttributeMaxDynamicSharedMemorySize, SMEM_TC);
    cudaFuncSetAttribute(mma_gemm_kernel<1, false, false>,
                         cudaFuncAttributeMaxDynamicSharedMemorySize, SMEM_TC);
    cudaFuncSetAttribute(mma_gemm_kernel<3, true, true>,
                         cudaFuncAttributeMaxDynamicSharedMemorySize, SMEM_TC);
    cudaFuncSetAttribute(mma_gemm_kernel<3, true, false>,
                         cudaFuncAttributeMaxDynamicSharedMemorySize, SMEM_TC);

    // one fused prep launch
    prep_all_kernel<<<(PREP_TOTAL + 255) / 256, 256>>>(
        x, proj_w, k_w, v_w, q_w, out_w, skip_w, conv_w,
        src, projP, kvwP, qwR, outwR, skipwR, convR);

    // proj: [2048,160] @ [2560,160]^T -> tgt (viewed as [10240,512]); rounded
    mma_gemm_kernel<1, false, true><<<dim3(PROJ5 / 128, S_LEN / 128), NTHREADS, SMEM_TC>>>(
        src, projP, proj_b, tgt, S_LEN, PROJ5, KPAD);
    // q: [10240,512] @ [512,512]^T  (attention consumer -> no round)
    mma_gemm_kernel<1, false, false><<<dim3(DIM / 128, L_LEN / 128), NTHREADS, SMEM_TC>>>(
        tgt, qwR, in_b, q, L_LEN, DIM, DIM);
    // fused k+v: [2048,160] @ [1024,160]^T (bias in_b[512:1536] contiguous)
    mma_gemm_kernel<1, false, false><<<dim3(KVN / 128, S_LEN / 128), NTHREADS, SMEM_TC>>>(
        src, kvwP, in_b + DIM, kv, S_LEN, KVN, KPAD);

    banded_attn_kernel<<<L_LEN, dim3(32, HEADS)>>>(q, kv, o);

    // out projection (LN consumer -> no round)
    mma_gemm_kernel<1, false, false><<<dim3(DIM / 128, L_LEN / 128), NTHREADS, SMEM_TC>>>(
        o, outwR, out_b, ao, L_LEN, DIM, DIM);
    ln_add_kernel<<<L_LEN, 128>>>(ao, residual, cnn);

    // conv stack; layers 1,2 feed GEMMs (round), layer 3 feeds add_ln (no round)
    mma_gemm_kernel<3, true, true><<<dim3(DIM / 128, L_LEN / 128), NTHREADS, SMEM_TC>>>(
        cnn, convR + (size_t)0 * 3 * DIM * DIM, conv_b + 0 * DIM, h1, L_LEN, DIM, DIM);
    mma_gemm_kernel<3, true, true><<<dim3(DIM / 128, L_LEN / 128), NTHREADS, SMEM_TC>>>(
        h1, convR + (size_t)1 * 3 * DIM * DIM, conv_b + 1 * DIM, h2, L_LEN, DIM, DIM);
    mma_gemm_kernel<3, true, false><<<dim3(DIM / 128, L_LEN / 128), NTHREADS, SMEM_TC>>>(
        h2, convR + (size_t)2 * 3 * DIM * DIM, conv_b + 2 * DIM, h1, L_LEN, DIM, DIM);

    // skip (reuse q buffer; add_ln consumer -> no round)
    mma_gemm_kernel<1, false, false><<<dim3(DIM / 128, L_LEN / 128), NTHREADS, SMEM_TC>>>(
        cnn, skipwR, skip_b, q, L_LEN, DIM, DIM);

    add_ln_kernel<<<L_LEN, 128>>>(h1, q, out);
}

// round 17
// speedup vs baseline: 1.5044x; 1.5044x over previous
#include <cuda_runtime.h>
#include <cuda_fp16.h>
#include <cstdint>

// ---------------------------------------------------------------------------
// Problem constants
// ---------------------------------------------------------------------------
#define S_LEN   2048
#define L_LEN   10240        // 5*S
#define DIM     512
#define PROJ    128
#define KDIM    136          // PROJ + NPOS
#define KPAD    160          // KDIM padded to multiple of 32
#define HEADS   4
#define HD      128
#define PROJ5   2560         // DIM*5
#define KVN     1024         // merged k+v output width

// ---------------------------------------------------------------------------
// Static device scratch (fp16 for all GEMM operands, fp32 for LN inputs)
// ---------------------------------------------------------------------------
__device__ __half g_src  [S_LEN * KPAD];
__device__ __half g_tgt  [L_LEN * DIM];
__device__ __half g_qh   [L_LEN * DIM];
__device__ __half g_kv   [S_LEN * KVN];     // cols 0-511 = k, 512-1023 = v
__device__ __half g_o    [L_LEN * DIM];
__device__ float  g_ao   [L_LEN * DIM];
__device__ __half g_cnn  [L_LEN * DIM];
__device__ __half g_h1   [L_LEN * DIM];
__device__ __half g_h2   [L_LEN * DIM];
__device__ float  g_h3   [L_LEN * DIM];
__device__ float  g_skipf[L_LEN * DIM];
__device__ __half g_projP[PROJ5 * KPAD];
__device__ __half g_kvwP [KVN * KPAD];      // rows 0-511 = k_w, 512-1023 = v_w
__device__ __half g_qwH  [DIM * DIM];
__device__ __half g_outwH[DIM * DIM];
__device__ __half g_skipwH[DIM * DIM];
__device__ __half g_convH[3 * 3 * DIM * DIM];   // [layer][tap][co][ci]

// ---------------------------------------------------------------------------
// PTX helpers (baseline sm_80+: mma.sync fp16, cp.async, ldmatrix)
// ---------------------------------------------------------------------------
__device__ __forceinline__ uint32_t smem_u32(const void* p) {
    return (uint32_t)__cvta_generic_to_shared(p);
}

__device__ __forceinline__ void cp_async16(uint32_t dst, const void* src, int sz) {
    asm volatile("cp.async.cg.shared.global [%0], [%1], 16, %2;"
                 :: "r"(dst), "l"(src), "r"(sz) : "memory");
}
#define CP_COMMIT() asm volatile("cp.async.commit_group;" ::: "memory")
#define CP_WAIT(n)  asm volatile("cp.async.wait_group %0;" :: "n"(n) : "memory")

// fp16 MMA: D(f32) = A(f16) * B(f16) + D, m16n8k16
__device__ __forceinline__ void mma_fp16(float* c, const uint32_t* a, const uint32_t* b) {
    asm volatile(
        "mma.sync.aligned.m16n8k16.row.col.f32.f16.f16.f32 "
        "{%0,%1,%2,%3}, {%4,%5,%6,%7}, {%8,%9}, {%0,%1,%2,%3};"
        : "+f"(c[0]), "+f"(c[1]), "+f"(c[2]), "+f"(c[3])
        : "r"(a[0]), "r"(a[1]), "r"(a[2]), "r"(a[3]), "r"(b[0]), "r"(b[1]));
}

#define LDMATRIX_X4(r0, r1, r2, r3, addr) \
    asm volatile("ldmatrix.sync.aligned.m8n8.x4.shared.b16 {%0,%1,%2,%3}, [%4];" \
                 : "=r"(r0), "=r"(r1), "=r"(r2), "=r"(r3) : "r"(addr))

// ---------------------------------------------------------------------------
// fp16 tensor-core GEMM (m16n8k16: 2x K per tensor instruction vs tf32 k8,
// SAME 10-bit mantissa as tf32 -> equivalent precision; fp32 accumulate).
// 3-stage cp.async pipeline, 256 threads, warp grid 2(M)x4(N), tile 64x32.
// C[M,N] = A[M,K] @ B^T + bias (B: [TAPS][N][K] row-major, fp16).
// TAPS==3: conv1d k=3 pad=1 (A rows shifted by tap-1, zero at edges)
// SP: softplus epilogue.  OUTH: store fp16 (GEMM consumers) else fp32 (LN).
// smem rows: 32 halfs padded to 40 (80B stride; ldmatrix row addrs hit 8
// distinct 16B bank groups since 5*r mod 8 is a permutation).
// ---------------------------------------------------------------------------
#define BM 128
#define BN 128
#define BK 32
#define NSTAGE 3
#define NTHREADS 256
#define SSTR_H 40                              // halfs per smem row
#define TILE_B (128 * SSTR_H * 2)              // bytes per operand tile (10240)
#define STAGE_B (2 * TILE_B)                   // A + B (20480)
#define SMEM_TC (NSTAGE * STAGE_B)             // 61440 bytes

__device__ __forceinline__ float softplus_f(float x) {
    return fmaxf(x, 0.0f) + log1pf(expf(-fabsf(x)));
}

template<int TAPS, bool SP, bool OUTH>
__global__ __launch_bounds__(NTHREADS, 1)
void mma_gemm_kernel(const __half* __restrict__ A, const __half* __restrict__ Bw,
                     const float* __restrict__ bias, void* __restrict__ Cv,
                     int M, int N, int K) {
    extern __shared__ __align__(16) char smem[];
    const int tid = threadIdx.x;
    const int wid = tid >> 5, lane = tid & 31;
    const int g = lane >> 2, t4 = lane & 3;
    const int wm = wid >> 2, wn = wid & 3;       // 2 x 4 warp grid
    const int row0 = blockIdx.y * BM, col0 = blockIdx.x * BN;

    // per-lane ldmatrix byte offsets within the A / B tiles
    // A x4: lanes 0-15 -> rows (wm*64+mi*16 + lane&15) at k0; lanes 16-31 same rows at k0+8
    const uint32_t a_lane_off =
        (uint32_t)((wm * 64 + (lane & 15)) * SSTR_H * 2 + (lane >> 4) * 16);
    // B x4 (covers 2 n-tiles): row = wn*32 + j16*16 + (lane&7) + ((lane>>4)&1)*8, koff = ((lane>>3)&1)*8 halfs
    const uint32_t b_lane_off =
        (uint32_t)((wn * 32 + (lane & 7) + ((lane >> 4) & 1) * 8) * SSTR_H * 2
                   + ((lane >> 3) & 1) * 16);
    const uint32_t smem_b32 = smem_u32(smem);

    float acc[4][4][4];
    #pragma unroll
    for (int i = 0; i < 4; i++)
        #pragma unroll
        for (int j = 0; j < 4; j++)
            #pragma unroll
            for (int r = 0; r < 4; r++) acc[i][j][r] = 0.0f;

    const int kc = K / BK;
    const int nc = kc * TAPS;

    // tile row = 32 halfs = 64B = 4 x 16B; thread u -> row u>>2, chunk u&3
    auto load = [&](int c, int s) {
        const int tap = (TAPS == 3) ? (c / kc) : 0;
        const int k0 = (c - tap * kc) * BK;
        const uint32_t base = smem_b32 + (uint32_t)(s * STAGE_B);
        #pragma unroll
        for (int t = 0; t < 2; t++) {
            int u = tid + t * NTHREADS;
            int r = u >> 2, ch = u & 3;
            uint32_t dst = base + (uint32_t)(r * SSTR_H * 2 + ch * 16);
            int arow = row0 + r + (TAPS == 3 ? tap - 1 : 0);
            const __half* src = A;
            int sz = 0;
            if (!(TAPS == 3) || (arow >= 0 && arow < M)) {
                src = A + (size_t)arow * K + k0 + ch * 8;
                sz = 16;
            }
            cp_async16(dst, src, sz);
        }
        const __half* Bt = Bw + (TAPS == 3 ? (size_t)tap * N * K : 0);
        #pragma unroll
        for (int t = 0; t < 2; t++) {
            int u = tid + t * NTHREADS;
            int r = u >> 2, ch = u & 3;
            uint32_t dst = base + (uint32_t)(TILE_B + r * SSTR_H * 2 + ch * 16);
            const __half* src = Bt + (size_t)(col0 + r) * K + k0 + ch * 8;
            cp_async16(dst, src, 16);
        }
        CP_COMMIT();
    };

    load(0, 0);
    load(1, 1);

    int stage = 0;
    for (int c = 0; c < nc; c++) {
        CP_WAIT(1);                      // in-order groups: chunk c resident
        __syncthreads();                 // all warps done with stage (c+2)%NSTAGE
        if (c + 2 < nc) load(c + 2, (c + 2) % NSTAGE);
        else CP_COMMIT();                // keep group count constant for CP_WAIT(1)

        const uint32_t sbase = smem_b32 + (uint32_t)(stage * STAGE_B);
        const uint32_t a_base = sbase + a_lane_off;
        const uint32_t b_base = sbase + (uint32_t)TILE_B + b_lane_off;
        #pragma unroll
        for (int kk = 0; kk < 2; kk++) {           // K=16 per step
            uint32_t af[4][4];
            #pragma unroll
            for (int i = 0; i < 4; i++)
                LDMATRIX_X4(af[i][0], af[i][1], af[i][2], af[i][3],
                            a_base + (uint32_t)(i * 16 * SSTR_H * 2) + (uint32_t)(kk * 32));
            uint32_t bf[4][2];
            #pragma unroll
            for (int p = 0; p < 2; p++)            // two x4, each covers 2 n-tiles
                LDMATRIX_X4(bf[2 * p][0], bf[2 * p][1], bf[2 * p + 1][0], bf[2 * p + 1][1],
                            b_base + (uint32_t)(p * 16 * SSTR_H * 2) + (uint32_t)(kk * 32));
            #pragma unroll
            for (int i = 0; i < 4; i++)
                #pragma unroll
                for (int j = 0; j < 4; j++)
                    mma_fp16(acc[i][j], af[i], bf[j]);
        }
        stage = (stage + 1 < NSTAGE) ? stage + 1 : 0;
    }

    // epilogue: bias (+softplus), store fp16 or fp32
    #pragma unroll
    for (int i = 0; i < 4; i++) {
        const int m = row0 + wm * 64 + i * 16 + g;
        #pragma unroll
        for (int j = 0; j < 4; j++) {
            const int n = col0 + wn * 32 + j * 8 + 2 * t4;
            const float b0 = bias[n], b1 = bias[n + 1];
            float v0 = acc[i][j][0] + b0, v1 = acc[i][j][1] + b1;
            float v2 = acc[i][j][2] + b0, v3 = acc[i][j][3] + b1;
            if (SP) {
                v0 = softplus_f(v0); v1 = softplus_f(v1);
                v2 = softplus_f(v2); v3 = softplus_f(v3);
            }
            if (OUTH) {
                __half* C = (__half*)Cv;
                *(__half2*)(C + (size_t)m * N + n)       = __floats2half2_rn(v0, v1);
                *(__half2*)(C + (size_t)(m + 8) * N + n) = __floats2half2_rn(v2, v3);
            } else {
                float* C = (float*)Cv;
                *(float2*)(C + (size_t)m * N + n)       = make_float2(v0, v1);
                *(float2*)(C + (size_t)(m + 8) * N + n) = make_float2(v2, v3);
            }
        }
    }
}

// ---------------------------------------------------------------------------
// Fused prep kernel: all input conditioning (fp32 -> fp16) in one launch.
// ---------------------------------------------------------------------------
#define PREP_SRC    (S_LEN * KPAD)
#define PREP_PROJ   (PROJ5 * KPAD)
#define PREP_KVW    (KVN * KPAD)
#define PREP_W      (DIM * DIM)
#define PREP_CONV   (3 * 3 * DIM * DIM)
#define PREP_TOTAL  (PREP_SRC + PREP_PROJ + PREP_KVW + 3 * PREP_W + PREP_CONV)

__global__ void prep_all_kernel(const float* __restrict__ x,
                                const float* __restrict__ proj_w,
                                const float* __restrict__ k_w,
                                const float* __restrict__ v_w,
                                const float* __restrict__ q_w,
                                const float* __restrict__ out_w,
                                const float* __restrict__ skip_w,
                                const float* __restrict__ conv_w,
                                __half* __restrict__ src,
                                __half* __restrict__ projP,
                                __half* __restrict__ kvwP,
                                __half* __restrict__ qwH,
                                __half* __restrict__ outwH,
                                __half* __restrict__ skipwH,
                                __half* __restrict__ convH) {
    int idx = blockIdx.x * blockDim.x + threadIdx.x;
    if (idx >= PREP_TOTAL) return;
    if (idx < PREP_SRC) {
        int n = idx / KPAD, c = idx % KPAD;
        float val = 0.0f;
        if (c < PROJ) val = x[n * PROJ + c];
        else if (c < KDIM) {
            int e = c - PROJ;
            int mod = n & ((2 << e) - 1);
            val = (float)mod / (float)(1 << e);   // exact in fp16 (<=8 mantissa bits)
        }
        src[idx] = __float2half_rn(val);
        return;
    }
    idx -= PREP_SRC;
    if (idx < PREP_PROJ) {
        int r = idx / KPAD, c = idx % KPAD;
        projP[idx] = __float2half_rn((c < KDIM) ? proj_w[r * KDIM + c] : 0.0f);
        return;
    }
    idx -= PREP_PROJ;
    if (idx < PREP_KVW) {
        int r = idx / KPAD, c = idx % KPAD;
        const float* W = (r < DIM) ? k_w : v_w;
        int rr = (r < DIM) ? r : r - DIM;
        kvwP[idx] = __float2half_rn((c < KDIM) ? W[rr * KDIM + c] : 0.0f);
        return;
    }
    idx -= PREP_KVW;
    if (idx < PREP_W) { qwH[idx] = __float2half_rn(q_w[idx]); return; }
    idx -= PREP_W;
    if (idx < PREP_W) { outwH[idx] = __float2half_rn(out_w[idx]); return; }
    idx -= PREP_W;
    if (idx < PREP_W) { skipwH[idx] = __float2half_rn(skip_w[idx]); return; }
    idx -= PREP_W;
    {   // conv_w[li][co][ci][t] -> convH[li][t][co][ci]
        int ci = idx & (DIM - 1);
        int co = (idx >> 9) & (DIM - 1);
        int t  = (idx / (DIM * DIM)) % 3;
        int li = idx / (3 * DIM * DIM);
        convH[idx] = __float2half_rn(conv_w[(((size_t)li * DIM + co) * DIM + ci) * 3 + t]);
    }
}

// ---------------------------------------------------------------------------
// Banded attention (band width <= 27): one block/query, one warp/head.
// q/kv fp16, fp32 math, o fp16.  k = kv[:,0:512], v = kv[:,512:1024]
// ---------------------------------------------------------------------------
__device__ __forceinline__ float4 ld4h(const __half* p) {
    uint2 raw = *(const uint2*)p;
    __half2 h0 = *(__half2*)&raw.x;
    __half2 h1 = *(__half2*)&raw.y;
    float2 f0 = __half22float2(h0);
    float2 f1 = __half22float2(h1);
    return make_float4(f0.x, f0.y, f1.x, f1.y);
}

__global__ void banded_attn_kernel(const __half* __restrict__ q, const __half* __restrict__ kv,
                                   __half* __restrict__ o) {
    int l = blockIdx.x;
    int h = threadIdx.y;
    int lane = threadIdx.x;
    int i_min = l > 64 ? (l - 64) / 5 : 0;
    int i_max = (l + 64) / 5;
    if (i_max > S_LEN - 1) i_max = S_LEN - 1;
    int cnt = i_max - i_min + 1;

    float4 qr = ld4h(q + (size_t)l * DIM + h * HD + lane * 4);
    const float scale = 0.0883883476483184f;

    float myscore = -1e30f;
    for (int j = 0; j < cnt; j++) {
        float4 kr = ld4h(kv + (size_t)(i_min + j) * KVN + h * HD + lane * 4);
        float d = qr.x * kr.x + qr.y * kr.y + qr.z * kr.z + qr.w * kr.w;
        #pragma unroll
        for (int off = 16; off; off >>= 1) d += __shfl_xor_sync(0xffffffffu, d, off);
        if (lane == j) myscore = d * scale;
    }
    float val = (lane < cnt) ? myscore : -1e30f;
    float mx = val;
    #pragma unroll
    for (int off = 16; off; off >>= 1)
        mx = fmaxf(mx, __shfl_xor_sync(0xffffffffu, mx, off));
    float e = (lane < cnt) ? expf(val - mx) : 0.0f;
    float sum = e;
    #pragma unroll
    for (int off = 16; off; off >>= 1) sum += __shfl_xor_sync(0xffffffffu, sum, off);
    float a = e / sum;

    float4 acc = make_float4(0.f, 0.f, 0.f, 0.f);
    for (int j = 0; j < cnt; j++) {
        float aj = __shfl_sync(0xffffffffu, a, j);
        float4 vr = ld4h(kv + (size_t)(i_min + j) * KVN + DIM + h * HD + lane * 4);
        acc.x += aj * vr.x; acc.y += aj * vr.y;
        acc.z += aj * vr.z; acc.w += aj * vr.w;
    }
    __half* op = o + (size_t)l * DIM + h * HD + lane * 4;
    uint2 packed;
    *(__half2*)&packed.x = __floats2half2_rn(acc.x, acc.y);
    *(__half2*)&packed.y = __floats2half2_rn(acc.z, acc.w);
    *(uint2*)op = packed;
}

// ---------------------------------------------------------------------------
// LayerNorm kernels
// ---------------------------------------------------------------------------
__device__ __forceinline__ void block_reduce_2(float& s, float& s2, int t) {
    #pragma unroll
    for (int off = 16; off; off >>= 1) {
        s  += __shfl_xor_sync(0xffffffffu, s,  off);
        s2 += __shfl_xor_sync(0xffffffffu, s2, off);
    }
    __shared__ float ss[4], ss2[4];
    if ((t & 31) == 0) { ss[t >> 5] = s; ss2[t >> 5] = s2; }
    __syncthreads();
    s  = ss[0] + ss[1] + ss[2] + ss[3];
    s2 = ss2[0] + ss2[1] + ss2[2] + ss2[3];
}

// cnn = fp16( LN(ao) + residual )   (feeds conv1 + skip GEMMs)
__global__ void ln_add_kernel(const float* __restrict__ z, const float* __restrict__ res,
                              __half* __restrict__ out) {
    int r = blockIdx.x;
    int t = threadIdx.x;
    float4 xv = ((const float4*)(z + (size_t)r * DIM))[t];
    float s  = xv.x + xv.y + xv.z + xv.w;
    float s2 = xv.x * xv.x + xv.y * xv.y + xv.z * xv.z + xv.w * xv.w;
    block_reduce_2(s, s2, t);
    float m = s * (1.0f / DIM);
    float var = s2 * (1.0f / DIM) - m * m;
    float rstd = rsqrtf(var + 1e-5f);
    float4 rv = ((const float4*)(res + (size_t)r * DIM))[t];
    uint2 packed;
    *(__half2*)&packed.x = __floats2half2_rn((xv.x - m) * rstd + rv.x,
                                             (xv.y - m) * rstd + rv.y);
    *(__half2*)&packed.y = __floats2half2_rn((xv.z - m) * rstd + rv.z,
                                             (xv.w - m) * rstd + rv.w);
    *(uint2*)(out + (size_t)r * DIM + t * 4) = packed;
}

// out = LN(h + sk)  (fp32 -> fp32, final output)
__global__ void add_ln_kernel(const float* __restrict__ h, const float* __restrict__ sk,
                              float* __restrict__ out) {
    int r = blockIdx.x;
    int t = threadIdx.x;
    float4 hv = ((const float4*)(h  + (size_t)r * DIM))[t];
    float4 kv = ((const float4*)(sk + (size_t)r * DIM))[t];
    float4 xv;
    xv.x = hv.x + kv.x; xv.y = hv.y + kv.y; xv.z = hv.z + kv.z; xv.w = hv.w + kv.w;
    float s  = xv.x + xv.y + xv.z + xv.w;
    float s2 = xv.x * xv.x + xv.y * xv.y + xv.z * xv.z + xv.w * xv.w;
    block_reduce_2(s, s2, t);
    float m = s * (1.0f / DIM);
    float var = s2 * (1.0f / DIM) - m * m;
    float rstd = rsqrtf(var + 1e-5f);
    float4 ov;
    ov.x = (xv.x - m) * rstd;
    ov.y = (xv.y - m) * rstd;
    ov.z = (xv.z - m) * rstd;
    ov.w = (xv.w - m) * rstd;
    ((float4*)(out + (size_t)r * DIM))[t] = ov;
}

// ---------------------------------------------------------------------------
// Launch
// ---------------------------------------------------------------------------
extern "C" void kernel_launch(void* const* d_in, const int* in_sizes, int n_in,
                              void* d_out, int out_size) {
    const float* x        = (const float*)d_in[0];
    const float* residual = (const float*)d_in[1];
    const float* proj_w   = (const float*)d_in[2];
    const float* proj_b   = (const float*)d_in[3];
    const float* q_w      = (const float*)d_in[4];
    const float* k_w      = (const float*)d_in[5];
    const float* v_w      = (const float*)d_in[6];
    const float* in_b     = (const float*)d_in[7];
    const float* out_w    = (const float*)d_in[8];
    const float* out_b    = (const float*)d_in[9];
    const float* conv_w   = (const float*)d_in[10];
    const float* conv_b   = (const float*)d_in[11];
    const float* skip_w   = (const float*)d_in[12];
    const float* skip_b   = (const float*)d_in[13];
    float* out = (float*)d_out;

    __half *src, *tgt, *qh, *kv, *o, *cnn, *h1, *h2;
    __half *projP, *kvwP, *qwH, *outwH, *skipwH, *convH;
    float *ao, *h3, *skipf;
    cudaGetSymbolAddress((void**)&src,    g_src);
    cudaGetSymbolAddress((void**)&tgt,    g_tgt);
    cudaGetSymbolAddress((void**)&qh,     g_qh);
    cudaGetSymbolAddress((void**)&kv,     g_kv);
    cudaGetSymbolAddress((void**)&o,      g_o);
    cudaGetSymbolAddress((void**)&ao,     g_ao);
    cudaGetSymbolAddress((void**)&cnn,    g_cnn);
    cudaGetSymbolAddress((void**)&h1,     g_h1);
    cudaGetSymbolAddress((void**)&h2,     g_h2);
    cudaGetSymbolAddress((void**)&h3,     g_h3);
    cudaGetSymbolAddress((void**)&skipf,  g_skipf);
    cudaGetSymbolAddress((void**)&projP,  g_projP);
    cudaGetSymbolAddress((void**)&kvwP,   g_kvwP);
    cudaGetSymbolAddress((void**)&qwH,    g_qwH);
    cudaGetSymbolAddress((void**)&outwH,  g_outwH);
    cudaGetSymbolAddress((void**)&skipwH, g_skipwH);
    cudaGetSymbolAddress((void**)&convH,  g_convH);

    cudaFuncSetAttribute(mma_gemm_kernel<1, false, true>,
                         cudaFuncAttributeMaxDynamicSharedMemorySize, SMEM_TC);
    cudaFuncSetAttribute(mma_gemm_kernel<1, false, false>,
                         cudaFuncAttributeMaxDynamicSharedMemorySize, SMEM_TC);
    cudaFuncSetAttribute(mma_gemm_kernel<3, true, true>,
                         cudaFuncAttributeMaxDynamicSharedMemorySize, SMEM_TC);
    cudaFuncSetAttribute(mma_gemm_kernel<3, true, false>,
                         cudaFuncAttributeMaxDynamicSharedMemorySize, SMEM_TC);

    // one fused prep launch (fp32 -> fp16 conditioning)
    prep_all_kernel<<<(PREP_TOTAL + 255) / 256, 256>>>(
        x, proj_w, k_w, v_w, q_w, out_w, skip_w, conv_w,
        src, projP, kvwP, qwH, outwH, skipwH, convH);

    // proj: [2048,160] @ [2560,160]^T -> tgt (viewed as [10240,512]), fp16 out
    mma_gemm_kernel<1, false, true><<<dim3(PROJ5 / 128, S_LEN / 128), NTHREADS, SMEM_TC>>>(
        src, projP, proj_b, tgt, S_LEN, PROJ5, KPAD);
    // q: [10240,512] @ [512,512]^T, fp16 out (attention consumer)
    mma_gemm_kernel<1, false, true><<<dim3(DIM / 128, L_LEN / 128), NTHREADS, SMEM_TC>>>(
        tgt, qwH, in_b, qh, L_LEN, DIM, DIM);
    // fused k+v: [2048,160] @ [1024,160]^T (bias in_b[512:1536] contiguous), fp16
    mma_gemm_kernel<1, false, true><<<dim3(KVN / 128, S_LEN / 128), NTHREADS, SMEM_TC>>>(
        src, kvwP, in_b + DIM, kv, S_LEN, KVN, KPAD);

    banded_attn_kernel<<<L_LEN, dim3(32, HEADS)>>>(qh, kv, o);

    // out projection -> fp32 (LN consumer)
    mma_gemm_kernel<1, false, false><<<dim3(DIM / 128, L_LEN / 128), NTHREADS, SMEM_TC>>>(
        o, outwH, out_b, ao, L_LEN, DIM, DIM);
    ln_add_kernel<<<L_LEN, 128>>>(ao, residual, cnn);

    // conv stack; layers 1,2 -> fp16 (GEMM consumers), layer 3 -> fp32 (add_ln)
    mma_gemm_kernel<3, true, true><<<dim3(DIM / 128, L_LEN / 128), NTHREADS, SMEM_TC>>>(
        cnn, convH + (size_t)0 * 3 * DIM * DIM, conv_b + 0 * DIM, h1, L_LEN, DIM, DIM);
    mma_gemm_kernel<3, true, true><<<dim3(DIM / 128, L_LEN / 128), NTHREADS, SMEM_TC>>>(
        h1, convH + (size_t)1 * 3 * DIM * DIM, conv_b + 1 * DIM, h2, L_LEN, DIM, DIM);
    mma_gemm_kernel<3, true, false><<<dim3(DIM / 128, L_LEN / 128), NTHREADS, SMEM_TC>>>(
        h2, convH + (size_t)2 * 3 * DIM * DIM, conv_b + 2 * DIM, h3, L_LEN, DIM, DIM);

    // skip -> fp32 (add_ln consumer)
    mma_gemm_kernel<1, false, false><<<dim3(DIM / 128, L_LEN / 128), NTHREADS, SMEM_TC>>>(
        cnn, skipwH, skip_b, skipf, L_LEN, DIM, DIM);

    add_ln_kernel<<<L_LEN, 128>>>(h3, skipf, out);
}